// round 13
// baseline (speedup 1.0000x reference)
#include <cuda_runtime.h>
#include <cstdint>
#include <cstddef>

#define NN 100000
#define NE 1600000
#define FD 128
#define NC 10
#define RP 12          // row stride floats: 10 feats + scalar chan + dis (48B)
#define NG 64
#define NB_N 391       // ceil(NN/256)
#define NBLK 740       // 148 SMs x 5 blocks -- co-resident via launch_bounds
#define NTHR 256
#define GSZ (NBLK * NTHR)

// ---------------- device scratch (allocation-free rule) ----------------
__device__ __align__(128) float g_z0[(size_t)NN * RP];  // dr*y0 row, s10=dr
__device__ __align__(128) float g_a1[(size_t)NN * RP];  // edge acc pass 1
__device__ __align__(128) float g_z1[(size_t)NN * RP];  // s10=t10*s2, s11=dc
__device__ __align__(128) float g_a2[(size_t)NN * RP];  // edge acc pass 2
__device__ int2  g_edges[NE];
__device__ float g_u[NN];
__device__ int   g_deg[NN];
__device__ float g_W12[FD * RP];
__device__ float g_c1[NC];
__device__ float g_pool[NG * NC];
__device__ float g_pu[NG];
__device__ float g_pv[NG];
__device__ int   g_cnt[NG];
__device__ int   g_is64;
__device__ int   g_count;          // barrier arrival counter (self-resetting)
__device__ volatile int g_gen;     // barrier generation (monotone across replays)

// ---------------- helpers ----------------
__device__ __forceinline__ int ld_idx(const void* p, long long i, int is64) {
    if (is64) return (int)((const long long*)p)[i];
    return ((const int*)p)[i];
}
__device__ __forceinline__ void red_add_v4(float* p, float4 v) {
    asm volatile("red.global.add.v4.f32 [%0], {%1,%2,%3,%4};"
                 :: "l"(p), "f"(v.x), "f"(v.y), "f"(v.z), "f"(v.w)
                 : "memory");
}

// software grid barrier (co-residency guaranteed by __launch_bounds__(,5)).
// threadfence both sides: release my STG/RED to L2; acquire invalidates L1D
// (gpu-scope fence -> CCTL.IVALL) so peer writes become visible.
__device__ __forceinline__ void gsync() {
    __syncthreads();
    if (threadIdx.x == 0) {
        int gen = g_gen;
        __threadfence();
        if (atomicAdd(&g_count, 1) == NBLK - 1) {
            g_count = 0;
            __threadfence();
            g_gen = gen + 1;
        } else {
            while (g_gen == gen) __nanosleep(64);
            __threadfence();
        }
    }
    __syncthreads();
}

// ---------------- kernels ----------------

// setup: zero accumulators, int64 probe, W12 = W1@W2, c1 = W2^T b1
__global__ void __launch_bounds__(256) k_setup(const float* __restrict__ W1,
                                               const float* __restrict__ W2,
                                               const float* __restrict__ b1,
                                               const unsigned* __restrict__ w) {
    int i = blockIdx.x * 256 + threadIdx.x;
    if (i < NN) g_deg[i] = 0;
    if (i < NG * NC) g_pool[i] = 0.f;
    if (i < NG) { g_pu[i] = 0.f; g_pv[i] = 0.f; g_cnt[i] = 0; }

    int b = blockIdx.x;
    int warp = threadIdx.x >> 5, lane = threadIdx.x & 31;

    if (b < 160) {                  // 1280 W12 outputs, warp per output
        int idx = b * 8 + warp;
        int k = idx / NC, c = idx - k * NC;
        float s = 0.f;
#pragma unroll
        for (int jj = 0; jj < 4; jj++) {
            int j = lane + jj * 32;
            s += W1[k * FD + j] * __ldg(W2 + j * NC + c);
        }
#pragma unroll
        for (int o = 16; o > 0; o >>= 1) s += __shfl_xor_sync(0xffffffffu, s, o);
        if (lane == 0) g_W12[k * RP + c] = s;
    } else if (b == 160) {          // c1
        if (warp < NC) {
            float s = 0.f;
#pragma unroll
            for (int jj = 0; jj < 4; jj++) {
                int j = lane + jj * 32;
                s += b1[j] * __ldg(W2 + j * NC + warp);
            }
#pragma unroll
            for (int o = 16; o > 0; o >>= 1) s += __shfl_xor_sync(0xffffffffu, s, o);
            if (lane == 0) g_c1[warp] = s;
        }
    } else if (b == 161) {          // probe: ids < 2^31 => int64 iff hi words 0
        __shared__ unsigned sprobe;
        if (threadIdx.x == 0) sprobe = 0u;
        __syncthreads();
        unsigned a = 0;
        for (int j = threadIdx.x; j < 4096; j += 256) a |= w[2 * j + 1];
        atomicOr(&sprobe, a);
        __syncthreads();
        if (threadIdx.x == 0) g_is64 = (sprobe == 0u) ? 1 : 0;
    }
}

// edge repack + in-degree; 2 edges/thread, vectorized
__global__ void k_prep(const void* __restrict__ ei) {
    int t = blockIdx.x * 256 + threadIdx.x;
    if (t >= NE / 2) return;
    int r0, r1, c0, c1;
    if (g_is64) {
        longlong2 rr = ((const longlong2*)ei)[t];
        longlong2 cc = ((const longlong2*)ei)[NE / 2 + t];
        r0 = (int)rr.x; r1 = (int)rr.y; c0 = (int)cc.x; c1 = (int)cc.y;
    } else {
        int2 rr = ((const int2*)ei)[t];
        int2 cc = ((const int2*)ei)[NE / 2 + t];
        r0 = rr.x; r1 = rr.y; c0 = cc.x; c1 = cc.y;
    }
    *(int4*)&g_edges[t * 2] = make_int4(r0, c0, r1, c1);
    atomicAdd(&g_deg[c0], 1);
    atomicAdd(&g_deg[c1], 1);
}

// z0 = dis*(X @ W12), slot10 = dis; zero a1. Warp-per-node, reg-heavy,
// runs as its own kernel so its 80 regs don't throttle the lean phases.
__global__ void __launch_bounds__(256) k_gemm0(const float* __restrict__ x) {
    int lane = threadIdx.x & 31;
    int warpId = (blockIdx.x * 256 + threadIdx.x) >> 5;
    int nWarps = (gridDim.x * 256) >> 5;

    float w[4][NC];
#pragma unroll
    for (int kk = 0; kk < 4; kk++)
#pragma unroll
        for (int c = 0; c < NC; c++)
            w[kk][c] = g_W12[(lane * 4 + kk) * RP + c];

    const float4 zero4 = make_float4(0.f, 0.f, 0.f, 0.f);
    for (int n = warpId; n < NN; n += nWarps) {
        float4 xv = *(const float4*)(x + (size_t)n * FD + lane * 4);
        float acc[NC];
#pragma unroll
        for (int c = 0; c < NC; c++) acc[c] = 0.f;
#pragma unroll
        for (int kk = 0; kk < 4; kk++) {
            float xk = ((const float*)&xv)[kk];
#pragma unroll
            for (int c = 0; c < NC; c++) acc[c] += xk * w[kk][c];
        }
#pragma unroll
        for (int o = 16; o > 0; o >>= 1)
#pragma unroll
            for (int c = 0; c < NC; c++)
                acc[c] += __shfl_xor_sync(0xffffffffu, acc[c], o);

        float d = rsqrtf((float)g_deg[n] + 1.0f);
        float* p = g_z0 + (size_t)n * RP;
        float* q = g_a1 + (size_t)n * RP;
        if (lane == 0)      *(float4*)p       = make_float4(acc[0]*d, acc[1]*d, acc[2]*d, acc[3]*d);
        else if (lane == 1) *(float4*)(p + 4) = make_float4(acc[4]*d, acc[5]*d, acc[6]*d, acc[7]*d);
        else if (lane == 2) *(float4*)(p + 8) = make_float4(acc[8]*d, acc[9]*d, d, 0.f);
        else if (lane == 4) *(float4*)q       = zero4;
        else if (lane == 5) *(float4*)(q + 4) = zero4;
        else if (lane == 6) *(float4*)(q + 8) = zero4;
    }
}

// persistent lean pipeline: sc1 | mid | sc2 | pool | fin, 4 grid barriers.
// launch_bounds(256,5) caps regs at 51 -> 1280 thr/SM = 62.5% occ.
extern "C" __global__ void __launch_bounds__(NTHR, 5)
k_rest(const void* __restrict__ batch, const float* __restrict__ b2,
       float* __restrict__ out)
{
    __shared__ float sp[NG * NC];
    __shared__ float su[NG], sv[NG];
    __shared__ int sc_[NG];

    int tid = threadIdx.x, bid = blockIdx.x;
    int gtid = bid * NTHR + tid;

    // ===== sc1: a1[c] += z0[r] (3 threads/edge)
    for (int gid = gtid; gid < NE * 3; gid += GSZ) {
        int e = gid / 3;
        int j = gid - e * 3;
        int2 rc = g_edges[e];
        float4 v = *(const float4*)(g_z0 + (size_t)rc.x * RP + j * 4);
        red_add_v4(g_a1 + (size_t)rc.y * RP + j * 4, v);
    }
    gsync();

    // ===== mid: z1 = dc^2*(a1+z0); u = dc*t10; z1 s11 = dc; zero a2
    for (int n = gtid; n < NN; n += GSZ) {
        const float* zp = g_z0 + (size_t)n * RP;
        const float* ap = g_a1 + (size_t)n * RP;
        float4 z0a = *(const float4*)zp,  z0b = *(const float4*)(zp + 4), z0c = *(const float4*)(zp + 8);
        float4 a0  = *(const float4*)ap,  a1  = *(const float4*)(ap + 4), a2  = *(const float4*)(ap + 8);
        float dc = z0c.z;
        float s2 = dc * dc;
        float t10 = a2.z + z0c.z;
        g_u[n] = dc * t10;
        float* d = g_z1 + (size_t)n * RP;
        *(float4*)d       = make_float4((a0.x+z0a.x)*s2, (a0.y+z0a.y)*s2, (a0.z+z0a.z)*s2, (a0.w+z0a.w)*s2);
        *(float4*)(d + 4) = make_float4((a1.x+z0b.x)*s2, (a1.y+z0b.y)*s2, (a1.z+z0b.z)*s2, (a1.w+z0b.w)*s2);
        *(float4*)(d + 8) = make_float4((a2.x+z0c.x)*s2, (a2.y+z0c.y)*s2, t10*s2, dc);
        const float4 zero4 = make_float4(0.f, 0.f, 0.f, 0.f);
        float* q = g_a2 + (size_t)n * RP;
        *(float4*)q = zero4; *(float4*)(q + 4) = zero4; *(float4*)(q + 8) = zero4;
    }
    gsync();

    // ===== sc2: a2[c] += z1[r]
    for (int gid = gtid; gid < NE * 3; gid += GSZ) {
        int e = gid / 3;
        int j = gid - e * 3;
        int2 rc = g_edges[e];
        float4 v = *(const float4*)(g_z1 + (size_t)rc.x * RP + j * 4);
        red_add_v4(g_a2 + (size_t)rc.y * RP + j * 4, v);
    }
    gsync();

    // ===== pool: y2 = dc*(a2+z1); v = dc*t10; shared combine then global
    for (int i = tid; i < NG * NC; i += NTHR) sp[i] = 0.f;
    if (tid < NG) { su[tid] = 0.f; sv[tid] = 0.f; sc_[tid] = 0; }
    __syncthreads();
    int is64 = g_is64;
    for (int n = gtid; n < NN; n += GSZ) {
        const float* zp = g_z1 + (size_t)n * RP;
        const float* ap = g_a2 + (size_t)n * RP;
        float4 z0a = *(const float4*)zp,  z0b = *(const float4*)(zp + 4), z0c = *(const float4*)(zp + 8);
        float4 a0  = *(const float4*)ap,  a1  = *(const float4*)(ap + 4), a2  = *(const float4*)(ap + 8);
        float t[11] = {a0.x+z0a.x, a0.y+z0a.y, a0.z+z0a.z, a0.w+z0a.w,
                       a1.x+z0b.x, a1.y+z0b.y, a1.z+z0b.z, a1.w+z0b.w,
                       a2.x+z0c.x, a2.y+z0c.y, a2.z+z0c.z};
        float dc = z0c.w;             // s11 = dis (from mid)
        int g = ld_idx(batch, n, is64);
        atomicAdd(&sc_[g], 1);
        atomicAdd(&su[g], g_u[n]);
        atomicAdd(&sv[g], dc * t[10]);
#pragma unroll
        for (int c = 0; c < NC; c++) atomicAdd(&sp[g * NC + c], dc * t[c]);
    }
    __syncthreads();
    for (int i = tid; i < NG * NC; i += NTHR)
        if (sp[i] != 0.f) atomicAdd(&g_pool[i], sp[i]);
    if (tid < NG) {
        if (sc_[tid]) atomicAdd(&g_cnt[tid], sc_[tid]);
        if (su[tid] != 0.f) atomicAdd(&g_pu[tid], su[tid]);
        if (sv[tid] != 0.f) atomicAdd(&g_pv[tid], sv[tid]);
    }
    gsync();

    // ===== fin: rank-1 bias combine + mean + log_softmax (block 0)
    if (bid == 0 && tid < NG) {
        int g = tid;
        float inv = 1.f / fmaxf((float)g_cnt[g], 1.f);
        float pu = g_pu[g], pv = g_pv[g];
        float v[NC];
        float m = -1e30f;
#pragma unroll
        for (int c = 0; c < NC; c++) {
            v[c] = (g_pool[g * NC + c] + pv * g_c1[c] + pu * __ldg(b2 + c)) * inv;
            m = fmaxf(m, v[c]);
        }
        float s = 0.f;
#pragma unroll
        for (int c = 0; c < NC; c++) s += expf(v[c] - m);
        float l = logf(s);
#pragma unroll
        for (int c = 0; c < NC; c++) out[g * NC + c] = v[c] - m - l;
    }
}

// ---------------- launch ----------------
extern "C" void kernel_launch(void* const* d_in, const int* in_sizes, int n_in,
                              void* d_out, int out_size) {
    const float* x = nullptr;
    const void* ei = nullptr;
    const void* batch = nullptr;
    const float *W1 = nullptr, *b1 = nullptr, *W2 = nullptr, *b2 = nullptr;

    for (int i = 0; i < n_in; i++) {
        switch (in_sizes[i]) {
            case 12800000: x = (const float*)d_in[i]; break;
            case 3200000:  ei = d_in[i]; break;
            case 100000:   batch = d_in[i]; break;
            case 16384:    W1 = (const float*)d_in[i]; break;
            case 128:      b1 = (const float*)d_in[i]; break;
            case 1280:     W2 = (const float*)d_in[i]; break;
            case 10:       b2 = (const float*)d_in[i]; break;
            default: break;
        }
    }
    const int NB_E2 = (NE / 2 + 255) / 256;

    k_setup<<<NB_N, 256>>>(W1, W2, b1, (const unsigned*)ei);
    k_prep<<<NB_E2, 256>>>(ei);
    k_gemm0<<<1184, 256>>>(x);
    k_rest<<<NBLK, NTHR>>>(batch, b2, (float*)d_out);
}

// round 17
// speedup vs baseline: 1.0818x; 1.0818x over previous
#include <cuda_runtime.h>
#include <cuda_fp16.h>
#include <cstdint>
#include <cstddef>

#define NN 100000
#define NE 1600000
#define FD 128
#define NC 10
#define RP 12          // fp32 z-row stride: 10 feats + scalar + dis (48B)
#define HP 16          // fp16 row stride in halves (32B = exactly 1 sector)
#define NG 64
#define NB_N 391       // ceil(NN/256)
#define NBLK 888       // 148 SMs x 6 blocks -- co-resident via launch_bounds
#define NTHR 256
#define GSZ (NBLK * NTHR)

// ---------------- device scratch (allocation-free rule) ----------------
__device__ __align__(128) float  g_z0[(size_t)NN * RP];   // dr*y0, s10=dr
__device__ __align__(128) __half g_z0h[(size_t)NN * HP];  // fp16 mirror, h10=dr
__device__ __align__(128) __half g_a1h[(size_t)NN * HP];  // fp16 edge acc 1
__device__ __align__(128) float  g_z1[(size_t)NN * RP];   // s10=t10*s2, s11=dc
__device__ __align__(128) __half g_z1h[(size_t)NN * HP];  // fp16 mirror
__device__ __align__(128) __half g_a2h[(size_t)NN * HP];  // fp16 edge acc 2
__device__ int2  g_edges[NE];
__device__ float g_u[NN];
__device__ int   g_deg[NN];
__device__ float g_W12[FD * RP];
__device__ float g_c1[NC];
__device__ float g_pool[NG * NC];
__device__ float g_pu[NG];
__device__ float g_pv[NG];
__device__ int   g_cnt[NG];
__device__ int   g_is64;
__device__ int   g_count;
__device__ volatile int g_gen;

// ---------------- helpers ----------------
__device__ __forceinline__ int ld_idx(const void* p, long long i, int is64) {
    if (is64) return (int)((const long long*)p)[i];
    return ((const int*)p)[i];
}
// vector fp16 reduction: adds 4 halves (two f16x2) in one 8B op, 1 sector
__device__ __forceinline__ void red_add_h4(__half* p, unsigned h0, unsigned h1) {
    asm volatile("red.global.add.noftz.v2.f16x2 [%0], {%1,%2};"
                 :: "l"(p), "r"(h0), "r"(h1) : "memory");
}
__device__ __forceinline__ unsigned h2u(float a, float b) {
    __half2 h = __floats2half2_rn(a, b);
    return *(unsigned*)&h;
}
__device__ __forceinline__ float2 u2f(unsigned u) {
    return __half22float2(*(__half2*)&u);
}

// software grid barrier (co-residency via __launch_bounds__(,6)).
__device__ __forceinline__ void gsync() {
    __syncthreads();
    if (threadIdx.x == 0) {
        int gen = g_gen;
        __threadfence();
        if (atomicAdd(&g_count, 1) == NBLK - 1) {
            g_count = 0;
            __threadfence();
            g_gen = gen + 1;
        } else {
            while (g_gen == gen) __nanosleep(64);
            __threadfence();
        }
    }
    __syncthreads();
}

// ---------------- kernels ----------------

// setup: zero pool accumulators + deg, int64 probe, W12 = W1@W2, c1 = W2^T b1
__global__ void __launch_bounds__(256) k_setup(const float* __restrict__ W1,
                                               const float* __restrict__ W2,
                                               const float* __restrict__ b1,
                                               const unsigned* __restrict__ w) {
    int i = blockIdx.x * 256 + threadIdx.x;
    if (i < NN) g_deg[i] = 0;
    if (i < NG * NC) g_pool[i] = 0.f;
    if (i < NG) { g_pu[i] = 0.f; g_pv[i] = 0.f; g_cnt[i] = 0; }

    int b = blockIdx.x;
    int warp = threadIdx.x >> 5, lane = threadIdx.x & 31;

    if (b < 160) {
        int idx = b * 8 + warp;
        int k = idx / NC, c = idx - k * NC;
        float s = 0.f;
#pragma unroll
        for (int jj = 0; jj < 4; jj++) {
            int j = lane + jj * 32;
            s += W1[k * FD + j] * __ldg(W2 + j * NC + c);
        }
#pragma unroll
        for (int o = 16; o > 0; o >>= 1) s += __shfl_xor_sync(0xffffffffu, s, o);
        if (lane == 0) g_W12[k * RP + c] = s;
    } else if (b == 160) {
        if (warp < NC) {
            float s = 0.f;
#pragma unroll
            for (int jj = 0; jj < 4; jj++) {
                int j = lane + jj * 32;
                s += b1[j] * __ldg(W2 + j * NC + warp);
            }
#pragma unroll
            for (int o = 16; o > 0; o >>= 1) s += __shfl_xor_sync(0xffffffffu, s, o);
            if (lane == 0) g_c1[warp] = s;
        }
    } else if (b == 161) {  // ids < 2^31 => int64 iff high words all zero
        __shared__ unsigned sprobe;
        if (threadIdx.x == 0) sprobe = 0u;
        __syncthreads();
        unsigned a = 0;
        for (int j = threadIdx.x; j < 4096; j += 256) a |= w[2 * j + 1];
        atomicOr(&sprobe, a);
        __syncthreads();
        if (threadIdx.x == 0) g_is64 = (sprobe == 0u) ? 1 : 0;
    }
}

// edge repack + in-degree; 2 edges/thread, vectorized
__global__ void k_prep(const void* __restrict__ ei) {
    int t = blockIdx.x * 256 + threadIdx.x;
    if (t >= NE / 2) return;
    int r0, r1, c0, c1;
    if (g_is64) {
        longlong2 rr = ((const longlong2*)ei)[t];
        longlong2 cc = ((const longlong2*)ei)[NE / 2 + t];
        r0 = (int)rr.x; r1 = (int)rr.y; c0 = (int)cc.x; c1 = (int)cc.y;
    } else {
        int2 rr = ((const int2*)ei)[t];
        int2 cc = ((const int2*)ei)[NE / 2 + t];
        r0 = rr.x; r1 = rr.y; c0 = cc.x; c1 = cc.y;
    }
    *(int4*)&g_edges[t * 2] = make_int4(r0, c0, r1, c1);
    atomicAdd(&g_deg[c0], 1);
    atomicAdd(&g_deg[c1], 1);
}

// z0 = dis*(X @ W12) fp32 + fp16 mirror; zero a1h. Warp-per-node, reg-heavy.
__global__ void __launch_bounds__(256) k_gemm0(const float* __restrict__ x) {
    int lane = threadIdx.x & 31;
    int warpId = (blockIdx.x * 256 + threadIdx.x) >> 5;
    int nWarps = (gridDim.x * 256) >> 5;

    float w[4][NC];
#pragma unroll
    for (int kk = 0; kk < 4; kk++)
#pragma unroll
        for (int c = 0; c < NC; c++)
            w[kk][c] = g_W12[(lane * 4 + kk) * RP + c];

    for (int n = warpId; n < NN; n += nWarps) {
        float4 xv = *(const float4*)(x + (size_t)n * FD + lane * 4);
        float acc[NC];
#pragma unroll
        for (int c = 0; c < NC; c++) acc[c] = 0.f;
#pragma unroll
        for (int kk = 0; kk < 4; kk++) {
            float xk = ((const float*)&xv)[kk];
#pragma unroll
            for (int c = 0; c < NC; c++) acc[c] += xk * w[kk][c];
        }
#pragma unroll
        for (int o = 16; o > 0; o >>= 1)
#pragma unroll
            for (int c = 0; c < NC; c++)
                acc[c] += __shfl_xor_sync(0xffffffffu, acc[c], o);

        float d = rsqrtf((float)g_deg[n] + 1.0f);
        float* p = g_z0 + (size_t)n * RP;
        __half* h = g_z0h + (size_t)n * HP;
        __half* q = g_a1h + (size_t)n * HP;
        const uint4 zero4 = make_uint4(0u, 0u, 0u, 0u);
        if (lane == 0)      *(float4*)p       = make_float4(acc[0]*d, acc[1]*d, acc[2]*d, acc[3]*d);
        else if (lane == 1) *(float4*)(p + 4) = make_float4(acc[4]*d, acc[5]*d, acc[6]*d, acc[7]*d);
        else if (lane == 2) *(float4*)(p + 8) = make_float4(acc[8]*d, acc[9]*d, d, 0.f);
        else if (lane == 3) *(uint4*)h = make_uint4(h2u(acc[0]*d, acc[1]*d), h2u(acc[2]*d, acc[3]*d),
                                                    h2u(acc[4]*d, acc[5]*d), h2u(acc[6]*d, acc[7]*d));
        else if (lane == 4) *(uint2*)(h + 8) = make_uint2(h2u(acc[8]*d, acc[9]*d), h2u(d, 0.f));
        else if (lane == 5) *(uint4*)q       = zero4;
        else if (lane == 6) *(uint4*)(q + 8) = zero4;
    }
}

// persistent lean pipeline: sc1 | mid | sc2 | pool | fin, 4 grid barriers.
// (256,6): 1536 thr/SM = 75% occ, 42-reg cap.
extern "C" __global__ void __launch_bounds__(NTHR, 6)
k_rest(const void* __restrict__ batch, const float* __restrict__ b2,
       float* __restrict__ out)
{
    __shared__ float sp[NG * NC];
    __shared__ float su[NG], sv[NG];
    __shared__ int sc_[NG];

    int tid = threadIdx.x, bid = blockIdx.x;
    int gtid = bid * NTHR + tid;

    // ===== sc1: a1h[c] += z0h[r]. 3 thr/edge, thread j: 8B load + 8B red.
#pragma unroll 4
    for (int gid = gtid; gid < NE * 3; gid += GSZ) {
        int e = gid / 3;
        int j = gid - e * 3;
        int2 rc = g_edges[e];
        uint2 v = *(const uint2*)(g_z0h + (size_t)rc.x * HP + j * 4);
        red_add_h4(g_a1h + (size_t)rc.y * HP + j * 4, v.x, v.y);
    }
    gsync();

    // ===== mid: z1 = dc^2*(a1+z0); u = dc*t10; z1 s11=dc; mirror; zero a2h
    for (int n = gtid; n < NN; n += GSZ) {
        const float* zp = g_z0 + (size_t)n * RP;
        const __half* ah = g_a1h + (size_t)n * HP;
        float4 z0a = *(const float4*)zp, z0b = *(const float4*)(zp + 4), z0c = *(const float4*)(zp + 8);
        uint4 A = *(const uint4*)ah;
        uint2 B = *(const uint2*)(ah + 8);
        float2 f0 = u2f(A.x), f1 = u2f(A.y), f2 = u2f(A.z), f3 = u2f(A.w);
        float2 f4 = u2f(B.x), f5 = u2f(B.y);
        float dc = z0c.z;
        float s2 = dc * dc;
        float t10 = f5.x + z0c.z;          // accumulated dr sums + self dr
        g_u[n] = dc * t10;
        float v0 = (f0.x+z0a.x)*s2, v1 = (f0.y+z0a.y)*s2, v2 = (f1.x+z0a.z)*s2, v3 = (f1.y+z0a.w)*s2;
        float v4 = (f2.x+z0b.x)*s2, v5 = (f2.y+z0b.y)*s2, v6 = (f3.x+z0b.z)*s2, v7 = (f3.y+z0b.w)*s2;
        float v8 = (f4.x+z0c.x)*s2, v9 = (f4.y+z0c.y)*s2, v10 = t10*s2;
        float* d = g_z1 + (size_t)n * RP;
        *(float4*)d       = make_float4(v0, v1, v2, v3);
        *(float4*)(d + 4) = make_float4(v4, v5, v6, v7);
        *(float4*)(d + 8) = make_float4(v8, v9, v10, dc);
        __half* h = g_z1h + (size_t)n * HP;
        *(uint4*)h       = make_uint4(h2u(v0,v1), h2u(v2,v3), h2u(v4,v5), h2u(v6,v7));
        *(uint2*)(h + 8) = make_uint2(h2u(v8,v9), h2u(v10, 0.f));
        __half* q = g_a2h + (size_t)n * HP;
        const uint4 zero4 = make_uint4(0u, 0u, 0u, 0u);
        *(uint4*)q = zero4; *(uint4*)(q + 8) = zero4;
    }
    gsync();

    // ===== sc2: a2h[c] += z1h[r]
#pragma unroll 4
    for (int gid = gtid; gid < NE * 3; gid += GSZ) {
        int e = gid / 3;
        int j = gid - e * 3;
        int2 rc = g_edges[e];
        uint2 v = *(const uint2*)(g_z1h + (size_t)rc.x * HP + j * 4);
        red_add_h4(g_a2h + (size_t)rc.y * HP + j * 4, v.x, v.y);
    }
    gsync();

    // ===== pool: y2 = dc*(a2+z1); v = dc*t10; shared combine then global
    for (int i = tid; i < NG * NC; i += NTHR) sp[i] = 0.f;
    if (tid < NG) { su[tid] = 0.f; sv[tid] = 0.f; sc_[tid] = 0; }
    __syncthreads();
    int is64 = g_is64;
    for (int n = gtid; n < NN; n += GSZ) {
        const float* zp = g_z1 + (size_t)n * RP;
        const __half* ah = g_a2h + (size_t)n * HP;
        float4 z0a = *(const float4*)zp, z0b = *(const float4*)(zp + 4), z0c = *(const float4*)(zp + 8);
        uint4 A = *(const uint4*)ah;
        uint2 B = *(const uint2*)(ah + 8);
        float2 f0 = u2f(A.x), f1 = u2f(A.y), f2 = u2f(A.z), f3 = u2f(A.w);
        float2 f4 = u2f(B.x), f5 = u2f(B.y);
        float t[11] = {f0.x+z0a.x, f0.y+z0a.y, f1.x+z0a.z, f1.y+z0a.w,
                       f2.x+z0b.x, f2.y+z0b.y, f3.x+z0b.z, f3.y+z0b.w,
                       f4.x+z0c.x, f4.y+z0c.y, f5.x+z0c.z};
        float dc = z0c.w;             // s11 = dis (from mid)
        int g = ld_idx(batch, n, is64);
        atomicAdd(&sc_[g], 1);
        atomicAdd(&su[g], g_u[n]);
        atomicAdd(&sv[g], dc * t[10]);
#pragma unroll
        for (int c = 0; c < NC; c++) atomicAdd(&sp[g * NC + c], dc * t[c]);
    }
    __syncthreads();
    for (int i = tid; i < NG * NC; i += NTHR)
        if (sp[i] != 0.f) atomicAdd(&g_pool[i], sp[i]);
    if (tid < NG) {
        if (sc_[tid]) atomicAdd(&g_cnt[tid], sc_[tid]);
        if (su[tid] != 0.f) atomicAdd(&g_pu[tid], su[tid]);
        if (sv[tid] != 0.f) atomicAdd(&g_pv[tid], sv[tid]);
    }
    gsync();

    // ===== fin: rank-1 bias combine + mean + log_softmax (block 0)
    if (bid == 0 && tid < NG) {
        int g = tid;
        float inv = 1.f / fmaxf((float)g_cnt[g], 1.f);
        float pu = g_pu[g], pv = g_pv[g];
        float v[NC];
        float m = -1e30f;
#pragma unroll
        for (int c = 0; c < NC; c++) {
            v[c] = (g_pool[g * NC + c] + pv * g_c1[c] + pu * __ldg(b2 + c)) * inv;
            m = fmaxf(m, v[c]);
        }
        float s = 0.f;
#pragma unroll
        for (int c = 0; c < NC; c++) s += expf(v[c] - m);
        float l = logf(s);
#pragma unroll
        for (int c = 0; c < NC; c++) out[g * NC + c] = v[c] - m - l;
    }
}

// ---------------- launch ----------------
extern "C" void kernel_launch(void* const* d_in, const int* in_sizes, int n_in,
                              void* d_out, int out_size) {
    const float* x = nullptr;
    const void* ei = nullptr;
    const void* batch = nullptr;
    const float *W1 = nullptr, *b1 = nullptr, *W2 = nullptr, *b2 = nullptr;

    for (int i = 0; i < n_in; i++) {
        switch (in_sizes[i]) {
            case 12800000: x = (const float*)d_in[i]; break;
            case 3200000:  ei = d_in[i]; break;
            case 100000:   batch = d_in[i]; break;
            case 16384:    W1 = (const float*)d_in[i]; break;
            case 128:      b1 = (const float*)d_in[i]; break;
            case 1280:     W2 = (const float*)d_in[i]; break;
            case 10:       b2 = (const float*)d_in[i]; break;
            default: break;
        }
    }
    const int NB_E2 = (NE / 2 + 255) / 256;

    k_setup<<<NB_N, 256>>>(W1, W2, b1, (const unsigned*)ei);
    k_prep<<<NB_E2, 256>>>(ei);
    k_gemm0<<<1184, 256>>>(x);
    k_rest<<<NBLK, NTHR>>>(batch, b2, (float*)d_out);   // slot 4 -> profiled
}